// round 11
// baseline (speedup 1.0000x reference)
#include <cuda_runtime.h>
#include <cuda_fp16.h>
#include <cstdint>

#define H_   32
#define W_   32
#define C_   512
#define CLS_ 1000
#define R_   64
#define B_   128
#define MROWS (B_ * C_)      // 65536
#define KDIM  1024           // W*H

// ---- GEMM tiling ----
#define TILE_M   128
#define KCHUNK   64          // fp16 per row = 128 B (one swizzle atom row)
#define NCHUNKS  16
// per-stage smem layout (bytes): A 16K | B 8K = 24K, x2 stages
#define A_OFF    0
#define B_OFF    16384
#define STAGE    24576
#define SMEM_DYN (2 * STAGE)   // 48 KB

#define SW(o) ((o) ^ (((o) >> 3) & 0x70))

// ---- static device scratch (no allocations allowed) ----
__device__ float g_part[512 * R_];                // per-CTA partials

// ===========================================================================
// PTX helpers — sm_80+ baseline only
// ===========================================================================
__device__ __forceinline__ uint32_t smem_u32(const void* p) {
    uint32_t a;
    asm("{ .reg .u64 t; cvta.to.shared.u64 t, %1; cvt.u32.u64 %0, t; }"
        : "=r"(a) : "l"(p));
    return a;
}
__device__ __forceinline__ void sts64(uint32_t a, uint32_t x, uint32_t y) {
    asm volatile("st.shared.v2.b32 [%0], {%1,%2};" :: "r"(a), "r"(x), "r"(y));
}
__device__ __forceinline__ void ldm4(uint32_t* r, uint32_t addr) {
    asm volatile("ldmatrix.sync.aligned.m8n8.x4.shared.b16 {%0,%1,%2,%3}, [%4];"
                 : "=r"(r[0]), "=r"(r[1]), "=r"(r[2]), "=r"(r[3]) : "r"(addr));
}
__device__ __forceinline__ void mma16816(float* c, const uint32_t* a, const uint32_t* b) {
    asm volatile(
        "mma.sync.aligned.m16n8k16.row.col.f32.f16.f16.f32 "
        "{%0,%1,%2,%3}, {%4,%5,%6,%7}, {%8,%9}, {%0,%1,%2,%3};"
        : "+f"(c[0]), "+f"(c[1]), "+f"(c[2]), "+f"(c[3])
        : "r"(a[0]), "r"(a[1]), "r"(a[2]), "r"(a[3]), "r"(b[0]), "r"(b[1]));
}
__device__ __forceinline__ uint32_t packh2(float a, float b) {
    __half2 h = __floats2half2_rn(a, b);
    return *reinterpret_cast<uint32_t*>(&h);
}

// ===========================================================================
// Kernel 1: fp16 mma.sync GEMM with in-CTA B generation + fused U3 reduce
//   grid 512, block 256 (8 warps: 4m x 2n), dyn smem 48K
//   B chunk s covers k = s*64..s*64+63  ->  w in {2s, 2s+1}, all h.
//   B[r][j] = U2[w][r]*U1[h][r],  w = 2s + (j>>5), h = j&31.
// ===========================================================================
__global__ __launch_bounds__(256, 2) void gemm_k(const float* __restrict__ x,
                                                 const float* __restrict__ U1,
                                                 const float* __restrict__ U2,
                                                 const float* __restrict__ U3) {
    extern __shared__ char dsm[];
    __shared__ float s_red[4][R_];
    __shared__ float su1T[R_][32];   // su1T[r][h] = U1[h][r]
    __shared__ float su2T[R_][32];   // su2T[r][w] = U2[w][r]

    const int tid  = threadIdx.x;
    const int wid  = tid >> 5;
    const int lane = tid & 31;
    const int m_warp = (wid >> 1) * 32;   // 0,32,64,96
    const int n_warp = (wid & 1) * 32;    // 0,32
    const long m0 = (long)blockIdx.x * TILE_M;

    const uint32_t sb = smem_u32(dsm);

    // A prefetch mapping: rows rb + it*16, cols f*4..f*4+3
    const int rb = tid >> 4;            // 0..15
    const int f  = tid & 15;            // 0..15

    // B generation mapping: r-row = tid>>2, j-quad q = tid&3 (16 j each)
    const int brow = tid >> 2;          // 0..63
    const int bq   = tid & 3;           // 0..3

    // ---- start A chunk 0 LDG first (longest latency) ----
    float4 pf[8];
    {
        const float* xg = x + m0 * KDIM;             // k0 = 0
#pragma unroll
        for (int it = 0; it < 8; it++)
            pf[it] = *(const float4*)(xg + (long)(rb + it * 16) * KDIM + f * 4);
    }

    // ---- load U1/U2 transposed into smem (2048 floats each) ----
#pragma unroll
    for (int it = 0; it < 8; it++) {
        int i = tid + it * 256;                      // 0..2047
        int hh = i >> 6, rr = i & 63;
        su1T[rr][hh] = U1[i];
        su2T[rr][hh] = U2[i];
    }
    __syncthreads();

    float acc[2][4][4];
#pragma unroll
    for (int i = 0; i < 2; i++)
#pragma unroll
        for (int j = 0; j < 4; j++)
#pragma unroll
            for (int e = 0; e < 4; e++) acc[i][j][e] = 0.0f;

    for (int s = 0; s < NCHUNKS; s++) {
        const uint32_t bb = sb + (uint32_t)(s & 1) * STAGE;

        // ---- A: convert prefetched chunk s regs -> fp16 swizzled smem ----
#pragma unroll
        for (int it = 0; it < 8; it++) {
            float4 v = pf[it];
            uint32_t hA = packh2(v.x, v.y);
            uint32_t hB = packh2(v.z, v.w);
            uint32_t sw = SW((uint32_t)((rb + it * 16) * 128 + f * 8));
            sts64(bb + A_OFF + sw, hA, hB);
        }

        // ---- B: generate chunk s from U1/U2 smem ----
        {
            const int w  = 2 * s + (bq >> 1);
            const int hb = (bq & 1) * 16;
            const float u2v = su2T[brow][w];
            float4 a0 = *(const float4*)&su1T[brow][hb];
            float4 a1 = *(const float4*)&su1T[brow][hb + 4];
            float4 a2 = *(const float4*)&su1T[brow][hb + 8];
            float4 a3 = *(const float4*)&su1T[brow][hb + 12];
            uint32_t p0 = packh2(u2v * a0.x, u2v * a0.y);
            uint32_t p1 = packh2(u2v * a0.z, u2v * a0.w);
            uint32_t p2 = packh2(u2v * a1.x, u2v * a1.y);
            uint32_t p3 = packh2(u2v * a1.z, u2v * a1.w);
            uint32_t p4 = packh2(u2v * a2.x, u2v * a2.y);
            uint32_t p5 = packh2(u2v * a2.z, u2v * a2.w);
            uint32_t p6 = packh2(u2v * a3.x, u2v * a3.y);
            uint32_t p7 = packh2(u2v * a3.z, u2v * a3.w);
            uint32_t base = (uint32_t)(brow * 128 + bq * 32);
            sts64(bb + B_OFF + SW(base + 0),  p0, p1);
            sts64(bb + B_OFF + SW(base + 8),  p2, p3);
            sts64(bb + B_OFF + SW(base + 16), p4, p5);
            sts64(bb + B_OFF + SW(base + 24), p6, p7);
        }

        // ---- issue A LDG for chunk s+1 (lands under MMA) ----
        if (s < NCHUNKS - 1) {
            const float* xg = x + m0 * KDIM + (s + 1) * KCHUNK;
#pragma unroll
            for (int it = 0; it < 8; it++)
                pf[it] = *(const float4*)(xg + (long)(rb + it * 16) * KDIM + f * 4);
        }

        __syncthreads();   // STS(s) visible; also guarantees MMA(s-1) done

        // ---- compute: 4 k16-steps ----
#pragma unroll
        for (int kk = 0; kk < 4; kk++) {
            uint32_t ah[2][4], bhh[2][4];
#pragma unroll
            for (int mi = 0; mi < 2; mi++) {
                uint32_t row = m_warp + mi * 16 + (lane & 15);
                uint32_t kb  = kk * 32 + (lane >> 4) * 16;
                ldm4(ah[mi], bb + A_OFF + SW(row * 128 + kb));
            }
#pragma unroll
            for (int nq = 0; nq < 2; nq++) {
                uint32_t g = lane >> 3;
                uint32_t n = n_warp + nq * 16 + ((g >> 1) << 3) + (lane & 7);
                uint32_t kb = kk * 32 + (g & 1) * 16;
                ldm4(bhh[nq], bb + B_OFF + SW(n * 128 + kb));
            }
#pragma unroll
            for (int mi = 0; mi < 2; mi++)
#pragma unroll
                for (int nj = 0; nj < 4; nj++)
                    mma16816(acc[mi][nj], ah[mi], &bhh[nj >> 1][(nj & 1) * 2]);
        }
        // no trailing barrier: next iter's STS targets the other stage, and
        // the next __syncthreads orders MMA(s) before writes to stage s&1.
    }

    // ---- epilogue: scale by U3[c,r], reduce 128 rows -> 64 partials ----
    // s_u3 uses dsm[0..8K) = stage-0 A area; last MMA (chunk 15) reads stage 1
    // (offset 24576+), so no overlap.
    float* s_u3 = (float*)dsm;
    const int c_base = (blockIdx.x & 3) * 128;
#pragma unroll
    for (int it = 0; it < 32; it++) {
        int idx = tid + it * 256;                      // 0..8191
        s_u3[idx] = U3[c_base * R_ + idx];
    }
    __syncthreads();

    float p[8];
#pragma unroll
    for (int j = 0; j < 8; j++) p[j] = 0.0f;
#pragma unroll
    for (int mi = 0; mi < 2; mi++)
#pragma unroll
        for (int pr = 0; pr < 2; pr++) {
            int rowl = m_warp + mi * 16 + pr * 8 + (lane >> 2);
            const float* w = s_u3 + rowl * R_;
#pragma unroll
            for (int nj = 0; nj < 4; nj++) {
                int col = n_warp + nj * 8 + (lane & 3) * 2;
                p[nj * 2 + 0] = fmaf(acc[mi][nj][pr * 2 + 0], w[col],     p[nj * 2 + 0]);
                p[nj * 2 + 1] = fmaf(acc[mi][nj][pr * 2 + 1], w[col + 1], p[nj * 2 + 1]);
            }
        }
#pragma unroll
    for (int o = 4; o < 32; o <<= 1)
#pragma unroll
        for (int j = 0; j < 8; j++)
            p[j] += __shfl_xor_sync(0xffffffffu, p[j], o);

    if (lane < 4) {
#pragma unroll
        for (int nj = 0; nj < 4; nj++) {
            int col = n_warp + nj * 8 + lane * 2;
            s_red[wid >> 1][col]     = p[nj * 2 + 0];
            s_red[wid >> 1][col + 1] = p[nj * 2 + 1];
        }
    }
    __syncthreads();
    if (tid < R_)
        g_part[blockIdx.x * R_ + tid] =
            s_red[0][tid] + s_red[1][tid] + s_red[2][tid] + s_red[3][tid];
}

// ===========================================================================
// Kernel 2: out[b,cls] = sum_r (sum_j part[4b+j,r]) * lam[r] * U4[cls,r]
// ===========================================================================
__global__ __launch_bounds__(256) void out_k(const float* __restrict__ lam,
                                             const float* __restrict__ U4,
                                             float* __restrict__ out) {
    const int b = blockIdx.x;
    const int tid = threadIdx.x;
    __shared__ float u[R_];
    if (tid < R_) {
        float s = g_part[(b * 4 + 0) * R_ + tid] + g_part[(b * 4 + 1) * R_ + tid]
                + g_part[(b * 4 + 2) * R_ + tid] + g_part[(b * 4 + 3) * R_ + tid];
        u[tid] = s * lam[tid];
    }
    __syncthreads();
    for (int cls = tid; cls < CLS_; cls += 256) {
        const float4* up = (const float4*)(U4 + cls * R_);
        float s = 0.0f;
#pragma unroll
        for (int j = 0; j < 16; j++) {
            float4 v = up[j];
            s = fmaf(u[j * 4 + 0], v.x, s);
            s = fmaf(u[j * 4 + 1], v.y, s);
            s = fmaf(u[j * 4 + 2], v.z, s);
            s = fmaf(u[j * 4 + 3], v.w, s);
        }
        out[b * CLS_ + cls] = s;
    }
}

// ===========================================================================
extern "C" void kernel_launch(void* const* d_in, const int* in_sizes, int n_in,
                              void* d_out, int out_size) {
    const float* x   = (const float*)d_in[0];   // (B, C, W, H)
    const float* U1  = (const float*)d_in[1];   // (H, R)
    const float* U2  = (const float*)d_in[2];   // (W, R)
    const float* U3  = (const float*)d_in[3];   // (C, R)
    const float* U4  = (const float*)d_in[4];   // (CLS, R)
    const float* lam = (const float*)d_in[5];   // (R,)
    float* out = (float*)d_out;                 // (B, CLS)

    cudaFuncSetAttribute(gemm_k, cudaFuncAttributeMaxDynamicSharedMemorySize, SMEM_DYN);

    gemm_k<<<MROWS / TILE_M, 256, SMEM_DYN>>>(x, U1, U2, U3);
    out_k<<<B_, 256>>>(lam, U4, out);
}

// round 12
// speedup vs baseline: 1.1648x; 1.1648x over previous
#include <cuda_runtime.h>
#include <cuda_fp16.h>
#include <cstdint>

#define H_   32
#define W_   32
#define C_   512
#define CLS_ 1000
#define R_   64
#define B_   128
#define MROWS (B_ * C_)      // 65536
#define KDIM  1024           // W*H

// ---- GEMM tiling ----
#define TILE_M   128
#define KCHUNK   64          // fp16 per row = 128 B (one swizzle atom row)
#define NCHUNKS  16
// per-stage smem layout (bytes): A 16K | B 8K = 24K, x2 stages
#define A_OFF    0
#define B_OFF    16384
#define STAGE    24576
#define SMEM_DYN (2 * STAGE)   // 48 KB

#define SW(o) ((o) ^ (((o) >> 3) & 0x70))

// ---- static device scratch (no allocations allowed) ----
__device__ __align__(16) __half g_M[R_ * KDIM];   // [r][k] fp16 merged U2*U1
__device__ float g_part[512 * R_];                // per-CTA partials

// ===========================================================================
// PTX helpers — sm_80+ baseline only
// ===========================================================================
__device__ __forceinline__ uint32_t smem_u32(const void* p) {
    uint32_t a;
    asm("{ .reg .u64 t; cvta.to.shared.u64 t, %1; cvt.u32.u64 %0, t; }"
        : "=r"(a) : "l"(p));
    return a;
}
__device__ __forceinline__ void sts64(uint32_t a, uint32_t x, uint32_t y) {
    asm volatile("st.shared.v2.b32 [%0], {%1,%2};" :: "r"(a), "r"(x), "r"(y));
}
__device__ __forceinline__ void cpasync16(uint32_t dst, const void* src) {
    asm volatile("cp.async.cg.shared.global [%0], [%1], 16;"
                 :: "r"(dst), "l"(src));
}
__device__ __forceinline__ void cp_commit() {
    asm volatile("cp.async.commit_group;");
}
template <int N>
__device__ __forceinline__ void cp_wait() {
    asm volatile("cp.async.wait_group %0;" :: "n"(N));
}
__device__ __forceinline__ void ldm4(uint32_t* r, uint32_t addr) {
    asm volatile("ldmatrix.sync.aligned.m8n8.x4.shared.b16 {%0,%1,%2,%3}, [%4];"
                 : "=r"(r[0]), "=r"(r[1]), "=r"(r[2]), "=r"(r[3]) : "r"(addr));
}
__device__ __forceinline__ void mma16816(float* c, const uint32_t* a, const uint32_t* b) {
    asm volatile(
        "mma.sync.aligned.m16n8k16.row.col.f32.f16.f16.f32 "
        "{%0,%1,%2,%3}, {%4,%5,%6,%7}, {%8,%9}, {%0,%1,%2,%3};"
        : "+f"(c[0]), "+f"(c[1]), "+f"(c[2]), "+f"(c[3])
        : "r"(a[0]), "r"(a[1]), "r"(a[2]), "r"(a[3]), "r"(b[0]), "r"(b[1]));
}

// ===========================================================================
// Kernel 0: M[r][k] = fp16( U2[w,r]*U1[h,r] ),  k = w*32+h
// ===========================================================================
__global__ __launch_bounds__(1024) void build_M(const float* __restrict__ U1,
                                                const float* __restrict__ U2) {
    __shared__ float su1[32], su2[32];
    const int r = blockIdx.x;
    if (threadIdx.x < 32)       su1[threadIdx.x]      = U1[threadIdx.x * R_ + r];
    else if (threadIdx.x < 64)  su2[threadIdx.x - 32] = U2[(threadIdx.x - 32) * R_ + r];
    __syncthreads();
    const int k = threadIdx.x;
    g_M[r * KDIM + k] = __float2half_rn(su2[k >> 5] * su1[k & 31]);
}

// ===========================================================================
// Kernel 1: pipelined fp16 mma.sync GEMM (128x64 tile, K=1024) + fused U3
//   row-reduce.  grid 512, block 256 (8 warps: 4m x 2n), dyn smem 48K
//   (R10 form — proven 68.3us total)
// ===========================================================================
__global__ __launch_bounds__(256, 2) void gemm_k(const float* __restrict__ x,
                                                 const float* __restrict__ U3) {
    extern __shared__ char dsm[];
    __shared__ float s_red[4][R_];

    const int tid  = threadIdx.x;
    const int wid  = tid >> 5;
    const int lane = tid & 31;
    const int m_warp = (wid >> 1) * 32;   // 0,32,64,96
    const int n_warp = (wid & 1) * 32;    // 0,32
    const long m0 = (long)blockIdx.x * TILE_M;

    const uint32_t sb = smem_u32(dsm);

    const int bn = tid >> 3;            // 0..31 (rows bn and bn+32)
    const int bj = tid & 7;             // 16B slot within 128B row
    const int rb = tid >> 4;            // 0..15
    const int f  = tid & 15;            // 0..15

    float acc[2][4][4];
#pragma unroll
    for (int i = 0; i < 2; i++)
#pragma unroll
        for (int j = 0; j < 4; j++)
#pragma unroll
            for (int e = 0; e < 4; e++) acc[i][j][e] = 0.0f;

    // ---- prologue: B chunk 0 via cp.async, A chunk 0 into registers ----
    {
#pragma unroll
        for (int it = 0; it < 2; it++) {
            int n = bn + it * 32;
            long go = (long)n * 2048 + bj * 16;      // k0 = 0
            uint32_t sw = SW((uint32_t)(n * 128 + bj * 16));
            cpasync16(sb + B_OFF + sw, (const char*)g_M + go);
        }
        cp_commit();
    }
    float4 pf[8];
    {
        const float* xg = x + m0 * KDIM;             // k0 = 0
#pragma unroll
        for (int it = 0; it < 8; it++)
            pf[it] = *(const float4*)(xg + (long)(rb + it * 16) * KDIM + f * 4);
    }

    for (int s = 0; s < NCHUNKS; s++) {
        const uint32_t bb = sb + (uint32_t)(s & 1) * STAGE;
        const uint32_t nb = sb + (uint32_t)((s + 1) & 1) * STAGE;

        // ---- issue B cp.async for chunk s+1 ----
        if (s < NCHUNKS - 1) {
            const int k1 = (s + 1) * KCHUNK;
#pragma unroll
            for (int it = 0; it < 2; it++) {
                int n = bn + it * 32;
                long go = (long)n * 2048 + k1 * 2 + bj * 16;
                uint32_t sw = SW((uint32_t)(n * 128 + bj * 16));
                cpasync16(nb + B_OFF + sw, (const char*)g_M + go);
            }
            cp_commit();
        }

        // ---- convert prefetched A regs -> fp16 swizzled smem ----
#pragma unroll
        for (int it = 0; it < 8; it++) {
            float4 v = pf[it];
            __half h0 = __float2half_rn(v.x);
            __half h1 = __float2half_rn(v.y);
            __half h2 = __float2half_rn(v.z);
            __half h3 = __float2half_rn(v.w);
            uint32_t hA = (uint32_t)__half_as_ushort(h0) | ((uint32_t)__half_as_ushort(h1) << 16);
            uint32_t hB = (uint32_t)__half_as_ushort(h2) | ((uint32_t)__half_as_ushort(h3) << 16);
            uint32_t sw = SW((uint32_t)((rb + it * 16) * 128 + f * 8));
            sts64(bb + A_OFF + sw, hA, hB);
        }

        // ---- issue A LDG for chunk s+1 (completes under MMA) ----
        if (s < NCHUNKS - 1) {
            const float* xg = x + m0 * KDIM + (s + 1) * KCHUNK;
#pragma unroll
            for (int it = 0; it < 8; it++)
                pf[it] = *(const float4*)(xg + (long)(rb + it * 16) * KDIM + f * 4);
        }

        if (s < NCHUNKS - 1) cp_wait<1>(); else cp_wait<0>();
        __syncthreads();

        // ---- compute: 4 k16-steps ----
#pragma unroll
        for (int kk = 0; kk < 4; kk++) {
            uint32_t ah[2][4], bhh[2][4];
#pragma unroll
            for (int mi = 0; mi < 2; mi++) {
                uint32_t row = m_warp + mi * 16 + (lane & 15);
                uint32_t kb  = kk * 32 + (lane >> 4) * 16;
                ldm4(ah[mi], bb + A_OFF + SW(row * 128 + kb));
            }
#pragma unroll
            for (int nq = 0; nq < 2; nq++) {
                uint32_t g = lane >> 3;
                uint32_t n = n_warp + nq * 16 + ((g >> 1) << 3) + (lane & 7);
                uint32_t kb = kk * 32 + (g & 1) * 16;
                ldm4(bhh[nq], bb + B_OFF + SW(n * 128 + kb));
            }
#pragma unroll
            for (int mi = 0; mi < 2; mi++)
#pragma unroll
                for (int nj = 0; nj < 4; nj++)
                    mma16816(acc[mi][nj], ah[mi], &bhh[nj >> 1][(nj & 1) * 2]);
        }
        __syncthreads();
    }

    // ---- epilogue: scale by U3[c,r], reduce 128 rows -> 64 partials ----
    float* s_u3 = (float*)dsm;
    const int c_base = (blockIdx.x & 3) * 128;
#pragma unroll
    for (int it = 0; it < 32; it++) {
        int idx = tid + it * 256;                      // 0..8191
        s_u3[idx] = U3[c_base * R_ + idx];
    }
    __syncthreads();

    float p[8];
#pragma unroll
    for (int j = 0; j < 8; j++) p[j] = 0.0f;
#pragma unroll
    for (int mi = 0; mi < 2; mi++)
#pragma unroll
        for (int pr = 0; pr < 2; pr++) {
            int rowl = m_warp + mi * 16 + pr * 8 + (lane >> 2);
            const float* w = s_u3 + rowl * R_;
#pragma unroll
            for (int nj = 0; nj < 4; nj++) {
                int col = n_warp + nj * 8 + (lane & 3) * 2;
                p[nj * 2 + 0] = fmaf(acc[mi][nj][pr * 2 + 0], w[col],     p[nj * 2 + 0]);
                p[nj * 2 + 1] = fmaf(acc[mi][nj][pr * 2 + 1], w[col + 1], p[nj * 2 + 1]);
            }
        }
#pragma unroll
    for (int o = 4; o < 32; o <<= 1)
#pragma unroll
        for (int j = 0; j < 8; j++)
            p[j] += __shfl_xor_sync(0xffffffffu, p[j], o);

    if (lane < 4) {
#pragma unroll
        for (int nj = 0; nj < 4; nj++) {
            int col = n_warp + nj * 8 + lane * 2;
            s_red[wid >> 1][col]     = p[nj * 2 + 0];
            s_red[wid >> 1][col + 1] = p[nj * 2 + 1];
        }
    }
    __syncthreads();
    if (tid < R_)
        g_part[blockIdx.x * R_ + tid] =
            s_red[0][tid] + s_red[1][tid] + s_red[2][tid] + s_red[3][tid];
}

// ===========================================================================
// Kernel 2: out[b,cls] = sum_r (sum_j part[4b+j,r]) * lam[r] * U4[cls,r]
//   grid 1024 = 8 class-chunks x 128 b, block 128: one class per thread.
// ===========================================================================
__global__ __launch_bounds__(128) void out_k(const float* __restrict__ lam,
                                             const float* __restrict__ U4,
                                             float* __restrict__ out) {
    const int b     = blockIdx.x & 127;     // 0..127
    const int chunk = blockIdx.x >> 7;      // 0..7
    const int tid   = threadIdx.x;

    __shared__ float u[R_];
    if (tid < R_) {
        float s = g_part[(b * 4 + 0) * R_ + tid] + g_part[(b * 4 + 1) * R_ + tid]
                + g_part[(b * 4 + 2) * R_ + tid] + g_part[(b * 4 + 3) * R_ + tid];
        u[tid] = s * lam[tid];
    }
    __syncthreads();

    const int cls = chunk * 125 + tid;      // 8 x 125 = 1000
    if (tid < 125) {
        const float4* up = (const float4*)(U4 + cls * R_);
        float s = 0.0f;
#pragma unroll
        for (int j = 0; j < 16; j++) {
            float4 v = up[j];
            s = fmaf(u[j * 4 + 0], v.x, s);
            s = fmaf(u[j * 4 + 1], v.y, s);
            s = fmaf(u[j * 4 + 2], v.z, s);
            s = fmaf(u[j * 4 + 3], v.w, s);
        }
        out[b * CLS_ + cls] = s;
    }
}

// ===========================================================================
extern "C" void kernel_launch(void* const* d_in, const int* in_sizes, int n_in,
                              void* d_out, int out_size) {
    const float* x   = (const float*)d_in[0];   // (B, C, W, H)
    const float* U1  = (const float*)d_in[1];   // (H, R)
    const float* U2  = (const float*)d_in[2];   // (W, R)
    const float* U3  = (const float*)d_in[3];   // (C, R)
    const float* U4  = (const float*)d_in[4];   // (CLS, R)
    const float* lam = (const float*)d_in[5];   // (R,)
    float* out = (float*)d_out;                 // (B, CLS)

    cudaFuncSetAttribute(gemm_k, cudaFuncAttributeMaxDynamicSharedMemorySize, SMEM_DYN);

    build_M<<<R_, 1024>>>(U1, U2);
    gemm_k<<<MROWS / TILE_M, 256, SMEM_DYN>>>(x, U3);
    out_k<<<1024, 128>>>(lam, U4, out);
}

// round 13
// speedup vs baseline: 1.1803x; 1.0133x over previous
#include <cuda_runtime.h>
#include <cuda_fp16.h>
#include <cstdint>

#define H_   32
#define W_   32
#define C_   512
#define CLS_ 1000
#define R_   64
#define B_   128
#define MROWS (B_ * C_)      // 65536
#define KDIM  1024           // W*H

// ---- GEMM tiling ----
#define TILE_M   128
#define KCHUNK   64          // fp16 per row = 128 B (one swizzle atom row)
#define NCHUNKS  16
// per-stage smem layout (bytes): A 16K | B 8K = 24K, x2 stages
#define A_OFF    0
#define B_OFF    16384
#define STAGE    24576
#define SMEM_DYN (2 * STAGE)   // 48 KB

#define SW(o) ((o) ^ (((o) >> 3) & 0x70))

// ---- static device scratch (no allocations allowed) ----
__device__ __align__(16) __half g_M[R_ * KDIM];   // [r][k] fp16 merged U2*U1
__device__ float g_part[512 * R_];                // per-CTA partials

// ===========================================================================
// PTX helpers — sm_80+ baseline only
// ===========================================================================
__device__ __forceinline__ uint32_t smem_u32(const void* p) {
    uint32_t a;
    asm("{ .reg .u64 t; cvta.to.shared.u64 t, %1; cvt.u32.u64 %0, t; }"
        : "=r"(a) : "l"(p));
    return a;
}
__device__ __forceinline__ void sts64(uint32_t a, uint32_t x, uint32_t y) {
    asm volatile("st.shared.v2.b32 [%0], {%1,%2};" :: "r"(a), "r"(x), "r"(y));
}
__device__ __forceinline__ void cpasync16(uint32_t dst, const void* src) {
    asm volatile("cp.async.cg.shared.global [%0], [%1], 16;"
                 :: "r"(dst), "l"(src));
}
__device__ __forceinline__ void cp_commit() {
    asm volatile("cp.async.commit_group;");
}
__device__ __forceinline__ void cp_wait0() {
    asm volatile("cp.async.wait_group 0;");
}
__device__ __forceinline__ void ldm4(uint32_t* r, uint32_t addr) {
    asm volatile("ldmatrix.sync.aligned.m8n8.x4.shared.b16 {%0,%1,%2,%3}, [%4];"
                 : "=r"(r[0]), "=r"(r[1]), "=r"(r[2]), "=r"(r[3]) : "r"(addr));
}
__device__ __forceinline__ void mma16816(float* c, const uint32_t* a, const uint32_t* b) {
    asm volatile(
        "mma.sync.aligned.m16n8k16.row.col.f32.f16.f16.f32 "
        "{%0,%1,%2,%3}, {%4,%5,%6,%7}, {%8,%9}, {%0,%1,%2,%3};"
        : "+f"(c[0]), "+f"(c[1]), "+f"(c[2]), "+f"(c[3])
        : "r"(a[0]), "r"(a[1]), "r"(a[2]), "r"(a[3]), "r"(b[0]), "r"(b[1]));
}

// ===========================================================================
// Kernel 0: M[r][k] = fp16( U2[w,r]*U1[h,r] ),  k = w*32+h
//   grid 256, block 256 — one thread per element, coalesced writes.
//   Within a warp: k consecutive -> same r, same w (broadcast U2), h = lane.
// ===========================================================================
__global__ __launch_bounds__(256) void build_M(const float* __restrict__ U1,
                                               const float* __restrict__ U2) {
    int idx = blockIdx.x * 256 + threadIdx.x;   // = r*1024 + k
    int r = idx >> 10, k = idx & 1023;
    int w = k >> 5, h = k & 31;
    g_M[idx] = __float2half_rn(U2[w * R_ + r] * U1[h * R_ + r]);
}

// ===========================================================================
// Kernel 1: pipelined fp16 mma.sync GEMM (128x64 tile, K=1024) + fused U3
//   row-reduce.  grid 512, block 256 (8 warps: 4m x 2n), dyn smem 48K.
//   SINGLE barrier per chunk: cp.async for B(s+1) issued post-barrier, so
//   barrier(s) orders MMA(s-1) (last reader of stage (s+1)%2) before all
//   writes into that stage.
// ===========================================================================
__global__ __launch_bounds__(256, 2) void gemm_k(const float* __restrict__ x,
                                                 const float* __restrict__ U3) {
    extern __shared__ char dsm[];
    __shared__ float s_red[4][R_];

    const int tid  = threadIdx.x;
    const int wid  = tid >> 5;
    const int lane = tid & 31;
    const int m_warp = (wid >> 1) * 32;   // 0,32,64,96
    const int n_warp = (wid & 1) * 32;    // 0,32
    const long m0 = (long)blockIdx.x * TILE_M;

    const uint32_t sb = smem_u32(dsm);

    const int bn = tid >> 3;            // 0..31 (rows bn and bn+32)
    const int bj = tid & 7;             // 16B slot within 128B row
    const int rb = tid >> 4;            // 0..15
    const int f  = tid & 15;            // 0..15

    float acc[2][4][4];
#pragma unroll
    for (int i = 0; i < 2; i++)
#pragma unroll
        for (int j = 0; j < 4; j++)
#pragma unroll
            for (int e = 0; e < 4; e++) acc[i][j][e] = 0.0f;

    // ---- prologue: B chunk 0 via cp.async, A chunk 0 into registers ----
    {
#pragma unroll
        for (int it = 0; it < 2; it++) {
            int n = bn + it * 32;
            long go = (long)n * 2048 + bj * 16;      // k0 = 0
            uint32_t sw = SW((uint32_t)(n * 128 + bj * 16));
            cpasync16(sb + B_OFF + sw, (const char*)g_M + go);
        }
        cp_commit();
    }
    float4 pf[8];
    {
        const float* xg = x + m0 * KDIM;             // k0 = 0
#pragma unroll
        for (int it = 0; it < 8; it++)
            pf[it] = *(const float4*)(xg + (long)(rb + it * 16) * KDIM + f * 4);
    }

    for (int s = 0; s < NCHUNKS; s++) {
        const uint32_t bb = sb + (uint32_t)(s & 1) * STAGE;
        const uint32_t nb = sb + (uint32_t)((s + 1) & 1) * STAGE;

        // ---- convert prefetched A regs -> fp16 swizzled smem (stage s%2;
        //      last read by MMA(s-2), ordered by barrier(s-1)) ----
#pragma unroll
        for (int it = 0; it < 8; it++) {
            float4 v = pf[it];
            __half h0 = __float2half_rn(v.x);
            __half h1 = __float2half_rn(v.y);
            __half h2 = __float2half_rn(v.z);
            __half h3 = __float2half_rn(v.w);
            uint32_t hA = (uint32_t)__half_as_ushort(h0) | ((uint32_t)__half_as_ushort(h1) << 16);
            uint32_t hB = (uint32_t)__half_as_ushort(h2) | ((uint32_t)__half_as_ushort(h3) << 16);
            uint32_t sw = SW((uint32_t)((rb + it * 16) * 128 + f * 8));
            sts64(bb + A_OFF + sw, hA, hB);
        }

        // ---- issue A LDG for chunk s+1 (completes under MMA) ----
        if (s < NCHUNKS - 1) {
            const float* xg = x + m0 * KDIM + (s + 1) * KCHUNK;
#pragma unroll
            for (int it = 0; it < 8; it++)
                pf[it] = *(const float4*)(xg + (long)(rb + it * 16) * KDIM + f * 4);
        }

        cp_wait0();          // B(s) landed (only outstanding group)
        __syncthreads();     // STS(s)+B(s) visible; MMA(s-1) complete everywhere

        // ---- issue B cp.async for chunk s+1 (stage (s+1)%2 now safe) ----
        if (s < NCHUNKS - 1) {
            const int k1 = (s + 1) * KCHUNK;
#pragma unroll
            for (int it = 0; it < 2; it++) {
                int n = bn + it * 32;
                long go = (long)n * 2048 + k1 * 2 + bj * 16;
                uint32_t sw = SW((uint32_t)(n * 128 + bj * 16));
                cpasync16(nb + B_OFF + sw, (const char*)g_M + go);
            }
            cp_commit();
        }

        // ---- compute: 4 k16-steps ----
#pragma unroll
        for (int kk = 0; kk < 4; kk++) {
            uint32_t ah[2][4], bhh[2][4];
#pragma unroll
            for (int mi = 0; mi < 2; mi++) {
                uint32_t row = m_warp + mi * 16 + (lane & 15);
                uint32_t kb  = kk * 32 + (lane >> 4) * 16;
                ldm4(ah[mi], bb + A_OFF + SW(row * 128 + kb));
            }
#pragma unroll
            for (int nq = 0; nq < 2; nq++) {
                uint32_t g = lane >> 3;
                uint32_t n = n_warp + nq * 16 + ((g >> 1) << 3) + (lane & 7);
                uint32_t kb = kk * 32 + (g & 1) * 16;
                ldm4(bhh[nq], bb + B_OFF + SW(n * 128 + kb));
            }
#pragma unroll
            for (int mi = 0; mi < 2; mi++)
#pragma unroll
                for (int nj = 0; nj < 4; nj++)
                    mma16816(acc[mi][nj], ah[mi], &bhh[nj >> 1][(nj & 1) * 2]);
        }
        // single barrier per chunk — next iteration's barrier provides the
        // write-after-read protection for stage s%2.
    }
    __syncthreads();   // MMA(15) (reads stage 1) done before s_u3 overwrites it

    // ---- epilogue: scale by U3[c,r], reduce 128 rows -> 64 partials ----
    float* s_u3 = (float*)dsm;                     // 32 KB, spans both stages
    const int c_base = (blockIdx.x & 3) * 128;
#pragma unroll
    for (int it = 0; it < 32; it++) {
        int idx = tid + it * 256;                  // 0..8191
        s_u3[idx] = U3[c_base * R_ + idx];
    }
    __syncthreads();

    float p[8];
#pragma unroll
    for (int j = 0; j < 8; j++) p[j] = 0.0f;
#pragma unroll
    for (int mi = 0; mi < 2; mi++)
#pragma unroll
        for (int pr = 0; pr < 2; pr++) {
            int rowl = m_warp + mi * 16 + pr * 8 + (lane >> 2);
            const float* w = s_u3 + rowl * R_;
#pragma unroll
            for (int nj = 0; nj < 4; nj++) {
                int col = n_warp + nj * 8 + (lane & 3) * 2;
                p[nj * 2 + 0] = fmaf(acc[mi][nj][pr * 2 + 0], w[col],     p[nj * 2 + 0]);
                p[nj * 2 + 1] = fmaf(acc[mi][nj][pr * 2 + 1], w[col + 1], p[nj * 2 + 1]);
            }
        }
#pragma unroll
    for (int o = 4; o < 32; o <<= 1)
#pragma unroll
        for (int j = 0; j < 8; j++)
            p[j] += __shfl_xor_sync(0xffffffffu, p[j], o);

    if (lane < 4) {
#pragma unroll
        for (int nj = 0; nj < 4; nj++) {
            int col = n_warp + nj * 8 + lane * 2;
            s_red[wid >> 1][col]     = p[nj * 2 + 0];
            s_red[wid >> 1][col + 1] = p[nj * 2 + 1];
        }
    }
    __syncthreads();
    if (tid < R_)
        g_part[blockIdx.x * R_ + tid] =
            s_red[0][tid] + s_red[1][tid] + s_red[2][tid] + s_red[3][tid];
}

// ===========================================================================
// Kernel 2: out[b,cls] = sum_r (sum_j part[4b+j,r]) * lam[r] * U4[cls,r]
//   grid 1024 = 8 class-chunks x 128 b, block 128: one class per thread.
// ===========================================================================
__global__ __launch_bounds__(128) void out_k(const float* __restrict__ lam,
                                             const float* __restrict__ U4,
                                             float* __restrict__ out) {
    const int b     = blockIdx.x & 127;     // 0..127
    const int chunk = blockIdx.x >> 7;      // 0..7
    const int tid   = threadIdx.x;

    __shared__ float u[R_];
    if (tid < R_) {
        float s = g_part[(b * 4 + 0) * R_ + tid] + g_part[(b * 4 + 1) * R_ + tid]
                + g_part[(b * 4 + 2) * R_ + tid] + g_part[(b * 4 + 3) * R_ + tid];
        u[tid] = s * lam[tid];
    }
    __syncthreads();

    const int cls = chunk * 125 + tid;      // 8 x 125 = 1000
    if (tid < 125) {
        const float4* up = (const float4*)(U4 + cls * R_);
        float s = 0.0f;
#pragma unroll
        for (int j = 0; j < 16; j++) {
            float4 v = up[j];
            s = fmaf(u[j * 4 + 0], v.x, s);
            s = fmaf(u[j * 4 + 1], v.y, s);
            s = fmaf(u[j * 4 + 2], v.z, s);
            s = fmaf(u[j * 4 + 3], v.w, s);
        }
        out[b * CLS_ + cls] = s;
    }
}

// ===========================================================================
extern "C" void kernel_launch(void* const* d_in, const int* in_sizes, int n_in,
                              void* d_out, int out_size) {
    const float* x   = (const float*)d_in[0];   // (B, C, W, H)
    const float* U1  = (const float*)d_in[1];   // (H, R)
    const float* U2  = (const float*)d_in[2];   // (W, R)
    const float* U3  = (const float*)d_in[3];   // (C, R)
    const float* U4  = (const float*)d_in[4];   // (CLS, R)
    const float* lam = (const float*)d_in[5];   // (R,)
    float* out = (float*)d_out;                 // (B, CLS)

    cudaFuncSetAttribute(gemm_k, cudaFuncAttributeMaxDynamicSharedMemorySize, SMEM_DYN);

    build_M<<<256, 256>>>(U1, U2);
    gemm_k<<<MROWS / TILE_M, 256, SMEM_DYN>>>(x, U3);
    out_k<<<1024, 128>>>(lam, U4, out);
}